// round 1
// baseline (speedup 1.0000x reference)
#include <cuda_runtime.h>
#include <cstdint>

// Problem constants (fixed by setup_inputs)
#define N_ 32768
#define D_ 512
#define Q_ 4
#define K_ 2048

// ---------------- device scratch (no allocations allowed) ----------------
__device__ float g_res[N_ * D_];               // residual buffer (64 MB)
__device__ float g_rn2[N_];                    // ||residual_n||^2 per stage
__device__ float g_en2[Q_ * K_];               // ||e_k||^2 per codebook (precomputed)
__device__ unsigned long long g_key[N_];       // packed (dist_bits<<32)|k
__device__ double g_loss[Q_];                  // per-stage sum of squared errors

// ---------------- init: residual = x, x_q = 0, losses = 0 ----------------
__global__ void init_kernel(const float* __restrict__ x, float* __restrict__ xq) {
    int i = blockIdx.x * blockDim.x + threadIdx.x;
    g_res[i] = x[i];
    xq[i] = 0.0f;
    if (i < Q_) g_loss[i] = 0.0;
}

// ---------------- codebook norms: one warp per (q,k) row ----------------
__global__ void cbnorm_kernel(const float* __restrict__ cbs) {
    int w = (blockIdx.x * blockDim.x + threadIdx.x) >> 5;
    int lane = threadIdx.x & 31;
    if (w >= Q_ * K_) return;
    const float4* row = reinterpret_cast<const float4*>(cbs + (size_t)w * D_);
    float ss = 0.0f;
#pragma unroll
    for (int i = 0; i < 4; i++) {
        float4 v = row[lane + i * 32];
        ss += v.x * v.x + v.y * v.y + v.z * v.z + v.w * v.w;
    }
#pragma unroll
    for (int off = 16; off > 0; off >>= 1)
        ss += __shfl_xor_sync(0xFFFFFFFFu, ss, off);
    if (lane == 0) g_en2[w] = ss;
}

// ---------------- per-stage prep: rn2 + reset keys ----------------
__global__ void prep_kernel() {
    int w = (blockIdx.x * blockDim.x + threadIdx.x) >> 5;
    int lane = threadIdx.x & 31;
    if (w >= N_) return;
    const float4* row = reinterpret_cast<const float4*>(g_res + (size_t)w * D_);
    float ss = 0.0f;
#pragma unroll
    for (int i = 0; i < 4; i++) {
        float4 v = row[lane + i * 32];
        ss += v.x * v.x + v.y * v.y + v.z * v.z + v.w * v.w;
    }
#pragma unroll
    for (int off = 16; off > 0; off >>= 1)
        ss += __shfl_xor_sync(0xFFFFFFFFu, ss, off);
    if (lane == 0) {
        g_rn2[w] = ss;
        g_key[w] = ~0ull;
    }
}

// ---------------- distance GEMM + argmin epilogue ----------------
// grid (N/128, K/128), 256 threads; 128x128 tile, BK=32, 8x8 per thread.
__global__ __launch_bounds__(256, 2)
void dist_argmin_kernel(const float* __restrict__ cb, int q) {
    __shared__ float As[32][132];
    __shared__ float Bs[32][132];
    __shared__ unsigned long long rowKey[128];

    const int tid = threadIdx.x;
    const int nBase = blockIdx.x * 128;
    const int kBase = blockIdx.y * 128;
    const int tx = tid & 15;
    const int ty = tid >> 4;

    if (tid < 128) rowKey[tid] = ~0ull;

    float acc[8][8];
#pragma unroll
    for (int i = 0; i < 8; i++)
#pragma unroll
        for (int j = 0; j < 8; j++) acc[i][j] = 0.0f;

    for (int d0 = 0; d0 < D_; d0 += 32) {
        __syncthreads();
#pragma unroll
        for (int l = 0; l < 4; l++) {
            int slot = tid + 256 * l;       // 0..1023 float4 slots
            int r = slot >> 3;              // 0..127 tile row
            int v = slot & 7;               // float4 within 32-wide chunk
            float4 a = *reinterpret_cast<const float4*>(
                &g_res[(size_t)(nBase + r) * D_ + d0 + v * 4]);
            As[v * 4 + 0][r] = a.x; As[v * 4 + 1][r] = a.y;
            As[v * 4 + 2][r] = a.z; As[v * 4 + 3][r] = a.w;
            float4 b = *reinterpret_cast<const float4*>(
                &cb[(size_t)(kBase + r) * D_ + d0 + v * 4]);
            Bs[v * 4 + 0][r] = b.x; Bs[v * 4 + 1][r] = b.y;
            Bs[v * 4 + 2][r] = b.z; Bs[v * 4 + 3][r] = b.w;
        }
        __syncthreads();
#pragma unroll
        for (int dd = 0; dd < 32; dd++) {
            float a[8], b[8];
            float4 t;
            t = *reinterpret_cast<const float4*>(&As[dd][ty * 8]);
            a[0] = t.x; a[1] = t.y; a[2] = t.z; a[3] = t.w;
            t = *reinterpret_cast<const float4*>(&As[dd][ty * 8 + 4]);
            a[4] = t.x; a[5] = t.y; a[6] = t.z; a[7] = t.w;
            t = *reinterpret_cast<const float4*>(&Bs[dd][tx * 4]);
            b[0] = t.x; b[1] = t.y; b[2] = t.z; b[3] = t.w;
            t = *reinterpret_cast<const float4*>(&Bs[dd][64 + tx * 4]);
            b[4] = t.x; b[5] = t.y; b[6] = t.z; b[7] = t.w;
#pragma unroll
            for (int i = 0; i < 8; i++)
#pragma unroll
                for (int j = 0; j < 8; j++)
                    acc[i][j] = fmaf(a[i], b[j], acc[i][j]);
        }
    }

    // Epilogue: d = (rn2 + en2) - 2*dot ; pack & argmin (ties -> smallest k,
    // matching jnp.argmin first-occurrence since distinct bit patterns order).
#pragma unroll
    for (int i = 0; i < 8; i++) {
        int n = nBase + ty * 8 + i;
        float rn2 = g_rn2[n];
        unsigned long long bestk = ~0ull;
#pragma unroll
        for (int j = 0; j < 8; j++) {
            int kcol = kBase + tx * 4 + ((j >> 2) << 6) + (j & 3);
            float dist = (rn2 + g_en2[q * K_ + kcol]) - 2.0f * acc[i][j];
            unsigned long long key =
                ((unsigned long long)__float_as_uint(dist) << 32) | (unsigned)kcol;
            if (key < bestk) bestk = key;
        }
        atomicMin(&rowKey[ty * 8 + i], bestk);
    }
    __syncthreads();
    if (tid < 128) atomicMin(&g_key[nBase + tid], rowKey[tid]);
}

// ---------------- gather + residual update + loss ----------------
// one warp per row
__global__ void update_kernel(const float* __restrict__ cb,
                              float* __restrict__ xq,
                              float* __restrict__ idx_out, int q) {
    int w = (blockIdx.x * blockDim.x + threadIdx.x) >> 5;
    int lane = threadIdx.x & 31;
    if (w >= N_) return;
    unsigned long long key = g_key[w];
    int k = (int)(unsigned)(key & 0xFFFFFFFFull);
    if (lane == 0) idx_out[(size_t)w * Q_ + q] = (float)k;

    const float4* e4 = reinterpret_cast<const float4*>(cb + (size_t)k * D_);
    float4* r4 = reinterpret_cast<float4*>(g_res + (size_t)w * D_);
    float4* x4 = reinterpret_cast<float4*>(xq + (size_t)w * D_);
    float ss = 0.0f;
#pragma unroll
    for (int i = 0; i < 4; i++) {
        int d = lane + i * 32;
        float4 e = e4[d];
        float4 r = r4[d];
        float4 xo = x4[d];
        float dx = e.x - r.x, dy = e.y - r.y, dz = e.z - r.z, dw = e.w - r.w;
        ss += dx * dx + dy * dy + dz * dz + dw * dw;
        r4[d] = make_float4(r.x - e.x, r.y - e.y, r.z - e.z, r.w - e.w);
        x4[d] = make_float4(xo.x + e.x, xo.y + e.y, xo.z + e.z, xo.w + e.w);
    }
#pragma unroll
    for (int off = 16; off > 0; off >>= 1)
        ss += __shfl_xor_sync(0xFFFFFFFFu, ss, off);
    if (lane == 0) atomicAdd(&g_loss[q], (double)ss);
}

// ---------------- finalize mean loss ----------------
__global__ void finalize_kernel(float* __restrict__ loss_out) {
    if (threadIdx.x == 0) {
        double s = 0.0;
#pragma unroll
        for (int qq = 0; qq < Q_; qq++) s += g_loss[qq];
        // loss_q = (1 + BETA) * mean_sq ; mean over Q stages
        double ml = (s * 1.25 / ((double)N_ * (double)D_)) / (double)Q_;
        *loss_out = (float)ml;
    }
}

// ---------------- launch ----------------
extern "C" void kernel_launch(void* const* d_in, const int* in_sizes, int n_in,
                              void* d_out, int out_size) {
    const float* x = (const float*)d_in[0];
    const float* cbs = (const float*)d_in[1];
    float* out = (float*)d_out;
    float* xq = out;                                  // [N, D]
    float* loss_out = out + (size_t)N_ * D_;          // scalar
    float* idx_out = out + (size_t)N_ * D_ + 1;       // [N, Q] as float

    init_kernel<<<(N_ * D_) / 256, 256>>>(x, xq);
    cbnorm_kernel<<<(Q_ * K_) / 8, 256>>>(cbs);

    for (int q = 0; q < Q_; q++) {
        const float* cb = cbs + (size_t)q * K_ * D_;
        prep_kernel<<<N_ / 8, 256>>>();
        dim3 grid(N_ / 128, K_ / 128);
        dist_argmin_kernel<<<grid, 256>>>(cb, q);
        update_kernel<<<N_ / 8, 256>>>(cb, xq, idx_out, q);
    }
    finalize_kernel<<<1, 32>>>(loss_out);
}